// round 13
// baseline (speedup 1.0000x reference)
#include <cuda_runtime.h>
#include <math.h>

// B=1, N=512, CS=384, CZ=128, H=8, C=128, PQ=8, PV=8
// feats per head = 32(o_pair)+128(o)+8(o_rel)+128(o_g)+16(norms) = 312; CAT=2496
// out = [s_out 512*384][g_out 512*128]

#define S1 0.05103103630798287f           // sqrt(1/384)
#define S2 0.57735026918962576f           // sqrt(1/3)
#define HWS 0.09622504486493763f          // sqrt(1/108)

// -------------------- scratch (device globals, no allocs) --------------------
__device__ float d_q[512 * 1024];
__device__ float d_kv[512 * 2048];
__device__ float d_qpl[512 * 192];
__device__ float d_kpl[512 * 192];
__device__ float d_vgl[512 * 128];
__device__ float d_qn[512 * 4];
__device__ float d_tr[512 * 3];
__device__ float d_hw[8];
__device__ float d_qe[8 * 512 * 160];
__device__ float d_ke[8 * 512 * 160];
__device__ float d_logits[8 * 512 * 512];
__device__ float d_vcat[512 * 2048];   // [j][h][v(128) | vgg(128)]
__device__ float d_oall[512 * 2048];   // [i][h][o(128) | og(128)]
__device__ float d_za[512 * 1024];     // [i][h][128]
__device__ float d_orel[512 * 64];     // [i][h*8+c]
__device__ float d_feats[512 * 2496];
__device__ float d_part[4 * 512 * 384];

// -------------------- helpers --------------------
__device__ __forceinline__ void qrot(float qw, float qx, float qy, float qz,
                                     float vx, float vy, float vz,
                                     float& ox, float& oy, float& oz) {
    float ux = qy * vz - qz * vy;
    float uy = qz * vx - qx * vz;
    float uz = qx * vy - qy * vx;
    float wx = qy * uz - qz * uy;
    float wy = qz * ux - qx * uz;
    float wz = qx * uy - qy * ux;
    ox = vx + 2.f * (qw * ux + wx);
    oy = vy + 2.f * (qw * uy + wy);
    oz = vz + 2.f * (qw * uz + wz);
}

__device__ __forceinline__ void mm16(float (&acc)[4][4],
                                     const float (*As)[72], const float (*Bs)[72],
                                     int ty, int tx) {
#pragma unroll
    for (int k = 0; k < 16; k++) {
        const float4 av = *(const float4*)&As[k][ty * 4];
        const float4 bv = *(const float4*)&Bs[k][tx * 4];
        acc[0][0] += av.x * bv.x; acc[0][1] += av.x * bv.y; acc[0][2] += av.x * bv.z; acc[0][3] += av.x * bv.w;
        acc[1][0] += av.y * bv.x; acc[1][1] += av.y * bv.y; acc[1][2] += av.y * bv.z; acc[1][3] += av.y * bv.w;
        acc[2][0] += av.z * bv.x; acc[2][1] += av.z * bv.y; acc[2][2] += av.z * bv.z; acc[2][3] += av.z * bv.w;
        acc[3][0] += av.w * bv.x; acc[3][1] += av.w * bv.y; acc[3][2] += av.w * bv.z; acc[3][3] += av.w * bv.w;
    }
}

// -------------------- K: frames --------------------
__global__ void k_frames(const float* __restrict__ T, const float* __restrict__ hwr) {
    int n = threadIdx.x;
    const float* t = T + n * 16;
    float a = t[0], b = t[1], c = t[2], d = t[3];
    float inv = 1.0f / sqrtf(a * a + b * b + c * c + d * d + 1e-8f);
    d_qn[n * 4 + 0] = a * inv;
    d_qn[n * 4 + 1] = b * inv;
    d_qn[n * 4 + 2] = c * inv;
    d_qn[n * 4 + 3] = d * inv;
    d_tr[n * 3 + 0] = t[4];
    d_tr[n * 3 + 1] = t[5];
    d_tr[n * 3 + 2] = t[6];
    if (n < 8) {
        float x = hwr[n];
        float sp = (x > 20.f) ? x : log1pf(expf(x));
        d_hw[n] = sp * HWS;
    }
}

// -------------------- generic tiled GEMMs (M,N mult64; K mult16) --------------------
__global__ void __launch_bounds__(256) gemm_nn(
    const float* __restrict__ A, const float* __restrict__ B, float* __restrict__ C,
    const float* __restrict__ bias, int K, int lda, int ldb, int ldc,
    long sA, long sB, long sC) {
    __shared__ float As[16][72];
    __shared__ float Bs[16][72];
    int tid = threadIdx.x;
    int tx = tid & 15, ty = tid >> 4;
    int mBase = blockIdx.y * 64, nBase = blockIdx.x * 64;
    A += (long)blockIdx.z * sA;
    B += (long)blockIdx.z * sB;
    C += (long)blockIdx.z * sC;
    float acc[4][4] = {};
    int ak = tid & 15, am = tid >> 4;
    int bn = tid & 63, bk = tid >> 6;
    for (int kk = 0; kk < K; kk += 16) {
#pragma unroll
        for (int p = 0; p < 4; p++)
            As[ak][am + p * 16] = A[(long)(mBase + am + p * 16) * lda + kk + ak];
#pragma unroll
        for (int p = 0; p < 4; p++)
            Bs[bk + p * 4][bn] = B[(long)(kk + bk + p * 4) * ldb + nBase + bn];
        __syncthreads();
        mm16(acc, As, Bs, ty, tx);
        __syncthreads();
    }
#pragma unroll
    for (int i2 = 0; i2 < 4; i2++) {
        long r = mBase + ty * 4 + i2;
#pragma unroll
        for (int j2 = 0; j2 < 4; j2++) {
            int cc = nBase + tx * 4 + j2;
            float v = acc[i2][j2];
            if (bias) v += bias[cc];
            C[r * ldc + cc] = v;
        }
    }
}

__global__ void __launch_bounds__(256) gemm_nt(
    const float* __restrict__ A, const float* __restrict__ B, float* __restrict__ C,
    int K, int lda, int ldb, int ldc, long sA, long sB, long sC) {
    __shared__ float As[16][72];
    __shared__ float Bs[16][72];
    int tid = threadIdx.x;
    int tx = tid & 15, ty = tid >> 4;
    int mBase = blockIdx.y * 64, nBase = blockIdx.x * 64;
    A += (long)blockIdx.z * sA;
    B += (long)blockIdx.z * sB;
    C += (long)blockIdx.z * sC;
    float acc[4][4] = {};
    int ak = tid & 15, am = tid >> 4;
    for (int kk = 0; kk < K; kk += 16) {
#pragma unroll
        for (int p = 0; p < 4; p++)
            As[ak][am + p * 16] = A[(long)(mBase + am + p * 16) * lda + kk + ak];
#pragma unroll
        for (int p = 0; p < 4; p++)
            Bs[ak][am + p * 16] = B[(long)(nBase + am + p * 16) * ldb + kk + ak];
        __syncthreads();
        mm16(acc, As, Bs, ty, tx);
        __syncthreads();
    }
#pragma unroll
    for (int i2 = 0; i2 < 4; i2++) {
        long r = mBase + ty * 4 + i2;
#pragma unroll
        for (int j2 = 0; j2 < 4; j2++) {
            int cc = nBase + tx * 4 + j2;
            C[r * ldc + cc] = acc[i2][j2];
        }
    }
}

// split-K GEMM writing per-chunk partials (deterministic; reduce kernel sums)
__global__ void __launch_bounds__(256) gemm_skp(
    const float* __restrict__ A, const float* __restrict__ B, float* __restrict__ C,
    int kc, int lda, int ldb, int ldc) {
    __shared__ float As[16][72];
    __shared__ float Bs[16][72];
    int tid = threadIdx.x;
    int tx = tid & 15, ty = tid >> 4;
    int mBase = blockIdx.y * 64, nBase = blockIdx.x * 64;
    int k0 = blockIdx.z * kc;
    C += (long)blockIdx.z * (512L * 384);
    float acc[4][4] = {};
    int ak = tid & 15, am = tid >> 4;
    int bn = tid & 63, bk = tid >> 6;
    for (int kk = k0; kk < k0 + kc; kk += 16) {
#pragma unroll
        for (int p = 0; p < 4; p++)
            As[ak][am + p * 16] = A[(long)(mBase + am + p * 16) * lda + kk + ak];
#pragma unroll
        for (int p = 0; p < 4; p++)
            Bs[bk + p * 4][bn] = B[(long)(kk + bk + p * 4) * ldb + nBase + bn];
        __syncthreads();
        mm16(acc, As, Bs, ty, tx);
        __syncthreads();
    }
#pragma unroll
    for (int i2 = 0; i2 < 4; i2++) {
        long r = mBase + ty * 4 + i2;
#pragma unroll
        for (int j2 = 0; j2 < 4; j2++) {
            int cc = nBase + tx * 4 + j2;
            C[r * ldc + cc] = acc[i2][j2];
        }
    }
}

__global__ void k_red(const float* __restrict__ b_out, float* __restrict__ out) {
    int idx = blockIdx.x * 256 + threadIdx.x;
    if (idx < 196608) {
        float v = d_part[idx] + d_part[196608 + idx] + d_part[2 * 196608 + idx] + d_part[3 * 196608 + idx];
        out[idx] = v + b_out[idx % 384];
    }
}

// -------------------- K: points + extended features + vcat --------------------
__global__ void k_points(const float* __restrict__ g, const float* __restrict__ W_mg) {
    __shared__ float wmg[1024];
    __shared__ float vgl[128], gsm[128];
    __shared__ float qf[4], tf[3], hws[8];
    __shared__ float qsq[64], ksq[64];
    int j = blockIdx.x;
    int t = threadIdx.x;  // 64 threads
    for (int idx = t; idx < 1024; idx += 64) wmg[idx] = W_mg[idx];
    for (int idx = t; idx < 128; idx += 64) {
        vgl[idx] = d_vgl[j * 128 + idx];
        gsm[idx] = g[j * 128 + idx];
    }
    if (t < 4) qf[t] = d_qn[j * 4 + t];
    if (t < 3) tf[t] = d_tr[j * 3 + t];
    if (t < 8) hws[t] = d_hw[t];
    __syncthreads();
    float qw = qf[0], qx = qf[1], qy = qf[2], qz = qf[3];
    float tx0 = tf[0], ty0 = tf[1], tz0 = tf[2];
    int h = t >> 3, p = t & 7;
    float hw = hws[h];

    // q point
    {
        float px = d_qpl[j * 192 + t], py = d_qpl[j * 192 + 64 + t], pz = d_qpl[j * 192 + 128 + t];
        float ax, ay, az;
        qrot(qw, qx, qy, qz, px, py, pz, ax, ay, az);
        ax += tx0; ay += ty0; az += tz0;
        qsq[t] = ax * ax + ay * ay + az * az;
        float* qe = d_qe + (h * 512 + j) * 160;
        qe[128 + p * 3 + 0] = ax * hw;
        qe[128 + p * 3 + 1] = ay * hw;
        qe[128 + p * 3 + 2] = az * hw;
    }
    // k point
    {
        float px = d_kpl[j * 192 + t], py = d_kpl[j * 192 + 64 + t], pz = d_kpl[j * 192 + 128 + t];
        float bx, by, bz;
        qrot(qw, qx, qy, qz, px, py, pz, bx, by, bz);
        bx += tx0; by += ty0; bz += tz0;
        ksq[t] = bx * bx + by * by + bz * bz;
        float* ke = d_ke + (h * 512 + j) * 160;
        ke[128 + p * 3 + 0] = bx;
        ke[128 + p * 3 + 1] = by;
        ke[128 + p * 3 + 2] = bz;
    }
    // channel copies: qe[0:128]=q*S1, ke[0:128]=k, vcat v half
    for (int idx = t; idx < 1024; idx += 64) {
        int h2 = idx >> 7, c = idx & 127;
        d_qe[(h2 * 512 + j) * 160 + c] = d_q[j * 1024 + idx] * S1;
        d_ke[(h2 * 512 + j) * 160 + c] = d_kv[j * 2048 + h2 * 256 + c];
        d_vcat[j * 2048 + h2 * 256 + c] = d_kv[j * 2048 + h2 * 256 + 128 + c];
    }
    // vgg: multivector mix + forward transform
    float mv[16];
#pragma unroll
    for (int c = 0; c < 16; c++) {
        float acc = 0.f;
#pragma unroll
        for (int ii = 0; ii < 8; ii++) acc += wmg[t * 16 + ii] * vgl[ii * 16 + c];
#pragma unroll
        for (int ii = 0; ii < 8; ii++) acc += wmg[t * 16 + 8 + ii] * gsm[ii * 16 + c];
        mv[c] = acc;
    }
    float o16[16];
    o16[0] = mv[0];
    qrot(qw, qx, qy, qz, mv[1], mv[2], mv[3], o16[1], o16[2], o16[3]);
    qrot(qw, qx, qy, qz, mv[4], mv[5], mv[6], o16[4], o16[5], o16[6]);
    {
        float w10 = mv[10];
        float rx, ry, rz;
        qrot(qw, qx, qy, qz, mv[7], mv[8], mv[9], rx, ry, rz);
        o16[7] = rx + w10 * tx0;
        o16[8] = ry + w10 * ty0;
        o16[9] = rz + w10 * tz0;
    }
#pragma unroll
    for (int c = 10; c < 16; c++) o16[c] = mv[c];
    float* vdst = d_vcat + j * 2048 + h * 256 + 128 + p * 16;
#pragma unroll
    for (int c = 0; c < 16; c++) vdst[c] = o16[c];

    __syncthreads();
    if (p == 0) {
        float qs = 0.f, ks = 0.f;
#pragma unroll
        for (int pp = 0; pp < 8; pp++) { qs += qsq[h * 8 + pp]; ks += ksq[h * 8 + pp]; }
        float* qe0 = d_qe + (h * 512 + j) * 160;
        float* ke0 = d_ke + (h * 512 + j) * 160;
        qe0[152] = -0.5f * hw * qs; qe0[153] = 1.f;
        ke0[152] = 1.f;             ke0[153] = -0.5f * hw * ks;
#pragma unroll
        for (int c = 154; c < 160; c++) { qe0[c] = 0.f; ke0[c] = 0.f; }
    }
}

// -------------------- K: z bias add into logits --------------------
__global__ void __launch_bounds__(256) k_zbias(const float* __restrict__ z,
                                               const float* __restrict__ W_b,
                                               const float* __restrict__ b_b) {
    int i = blockIdx.x;
    int t = threadIdx.x;
    int w = t >> 5, l = t & 31;
    int c0 = l * 4;
    float wreg[4][8];
#pragma unroll
    for (int k = 0; k < 4; k++)
#pragma unroll
        for (int h = 0; h < 8; h++) wreg[k][h] = W_b[(c0 + k) * 8 + h];
    float bb[8];
#pragma unroll
    for (int h = 0; h < 8; h++) bb[h] = b_b[h];

    for (int j = w; j < 512; j += 8) {
        const float4 zv = *(const float4*)(z + ((long)(i * 512 + j)) * 128 + c0);
        float acc[8];
#pragma unroll
        for (int h = 0; h < 8; h++)
            acc[h] = zv.x * wreg[0][h] + zv.y * wreg[1][h] + zv.z * wreg[2][h] + zv.w * wreg[3][h];
#pragma unroll
        for (int off = 16; off > 0; off >>= 1)
#pragma unroll
            for (int h = 0; h < 8; h++) acc[h] += __shfl_xor_sync(0xffffffffu, acc[h], off);
        if (l == 0) {
#pragma unroll
            for (int h = 0; h < 8; h++)
                d_logits[h * 262144 + i * 512 + j] += S2 * (acc[h] + bb[h]);
        }
    }
}

// -------------------- K: softmax rows --------------------
__global__ void k_softmax(const float* __restrict__ sw_) {
    __shared__ float red[256];
    int i = blockIdx.x, h = blockIdx.y, t = threadIdx.x;
    float sw = sw_[h];
    float* row = d_logits + h * 262144 + i * 512;
    float v0 = sw * row[t], v1 = sw * row[t + 256];
    float m = fmaxf(v0, v1);
    red[t] = m;
    __syncthreads();
    for (int s = 128; s > 0; s >>= 1) {
        if (t < s) red[t] = fmaxf(red[t], red[t + s]);
        __syncthreads();
    }
    m = red[0];
    __syncthreads();
    float e0 = expf(v0 - m), e1 = expf(v1 - m);
    red[t] = e0 + e1;
    __syncthreads();
    for (int s = 128; s > 0; s >>= 1) {
        if (t < s) red[t] += red[t + s];
        __syncthreads();
    }
    float inv = 1.f / red[0];
    row[t] = e0 * inv;
    row[t + 256] = e1 * inv;
}

// -------------------- K: za = sum_j a*z --------------------
__global__ void __launch_bounds__(128) k_za(const float* __restrict__ z) {
    __shared__ float a_s[4096];
    int i = blockIdx.x, t = threadIdx.x;  // 128
    for (int idx = t; idx < 4096; idx += 128) {
        int h = idx >> 9, j = idx & 511;
        a_s[idx] = d_logits[h * 262144 + i * 512 + j];
    }
    __syncthreads();
    float acc[8] = {};
    const float* zp = z + (long)i * 65536 + t;
    for (int j = 0; j < 512; j++) {
        float zv = zp[(long)j * 128];
#pragma unroll
        for (int h = 0; h < 8; h++) acc[h] += a_s[h * 512 + j] * zv;
    }
#pragma unroll
    for (int h = 0; h < 8; h++) d_za[i * 1024 + h * 128 + t] = acc[h];
}

// -------------------- K: o_rel (rel computed on the fly) --------------------
__global__ void __launch_bounds__(64) k_orel() {
    __shared__ float a_s[4096];
    __shared__ float rel_s[64][9];
    __shared__ float qf[4], tf[3];
    int i = blockIdx.x, t = threadIdx.x;  // 64
    if (t < 4) qf[t] = d_qn[i * 4 + t];
    if (t < 3) tf[t] = d_tr[i * 3 + t];
    for (int idx = t; idx < 4096; idx += 64) {
        int h = idx >> 9, j = idx & 511;
        a_s[idx] = d_logits[h * 262144 + i * 512 + j];
    }
    __syncthreads();
    float wi = qf[0], xi = qf[1], yi = qf[2], zi = qf[3];
    float aw = wi, ax = -xi, ay = -yi, az = -zi;  // conj
    int h = t >> 3, c = t & 7;
    float acc = 0.f;
    for (int tile = 0; tile < 8; tile++) {
        int j = tile * 64 + t;
        float bw = d_qn[j * 4], bx = d_qn[j * 4 + 1], by = d_qn[j * 4 + 2], bz = d_qn[j * 4 + 3];
        rel_s[t][0] = aw * bw - ax * bx - ay * by - az * bz;
        rel_s[t][1] = aw * bx + ax * bw + ay * bz - az * by;
        rel_s[t][2] = aw * by - ax * bz + ay * bw + az * bx;
        rel_s[t][3] = aw * bz + ax * by - ay * bx + az * bw;
        float dx = d_tr[j * 3] - tf[0], dy = d_tr[j * 3 + 1] - tf[1], dz2 = d_tr[j * 3 + 2] - tf[2];
        float rx, ry, rz;
        qrot(aw, ax, ay, az, dx, dy, dz2, rx, ry, rz);
        rel_s[t][4] = rx; rel_s[t][5] = ry; rel_s[t][6] = rz; rel_s[t][7] = 0.f;
        __syncthreads();
        const float* ah = a_s + h * 512 + tile * 64;
#pragma unroll 16
        for (int jj = 0; jj < 64; jj++) acc += ah[jj] * rel_s[jj][c];
        __syncthreads();
    }
    d_orel[i * 64 + t] = acc;
}

// -------------------- K: epilogue (inv transform, norms, feats, g_out) --------------------
__global__ void __launch_bounds__(256) k_epilogue(const float* __restrict__ W_dz,
                                                  const float* __restrict__ b_dz,
                                                  const float* __restrict__ W_geo,
                                                  float* __restrict__ out_g) {
    __shared__ float ogf[64][17];
    __shared__ float qf[4], tf[3];
    int i = blockIdx.x, t = threadIdx.x;  // 256
    if (t < 4) qf[t] = d_qn[i * 4 + t];
    if (t < 3) tf[t] = d_tr[i * 3 + t];
    __syncthreads();
    float* fr = d_feats + i * 2496;

    // o_pair = za @ W_dz + b_dz
    {
        int h = t >> 5, oc = t & 31;
        const float* za = d_za + i * 1024 + h * 128;
        float acc = b_dz[oc];
#pragma unroll 8
        for (int c = 0; c < 128; c++) acc += za[c] * W_dz[c * 32 + oc];
        fr[h * 312 + oc] = acc;
    }
    // o copy
    for (int idx = t; idx < 1024; idx += 256) {
        int h = idx >> 7, c = idx & 127;
        fr[h * 312 + 32 + c] = d_oall[i * 2048 + h * 256 + c];
    }
    // o_rel copy
    if (t < 64) fr[(t >> 3) * 312 + 160 + (t & 7)] = d_orel[i * 64 + t];
    // o_g inverse transform + norms
    if (t < 64) {
        int h = t >> 3, p = t & 7;
        float qw = qf[0], qx = -qf[1], qy = -qf[2], qz = -qf[3];  // conj
        const float* src = d_oall + i * 2048 + h * 256 + 128 + p * 16;
        float mv[16];
#pragma unroll
        for (int c = 0; c < 16; c++) mv[c] = src[c];
        float o16[16];
        o16[0] = mv[0];
        qrot(qw, qx, qy, qz, mv[1], mv[2], mv[3], o16[1], o16[2], o16[3]);
        qrot(qw, qx, qy, qz, mv[4], mv[5], mv[6], o16[4], o16[5], o16[6]);
        {
            float w10 = mv[10];
            qrot(qw, qx, qy, qz, mv[7] - w10 * tf[0], mv[8] - w10 * tf[1], mv[9] - w10 * tf[2],
                 o16[7], o16[8], o16[9]);
        }
#pragma unroll
        for (int c = 10; c < 16; c++) o16[c] = mv[c];
        float n1 = 0.f, n2 = 0.f;
#pragma unroll
        for (int c = 0; c < 10; c++) n1 += o16[c] * o16[c];
#pragma unroll
        for (int c = 10; c < 16; c++) n2 += o16[c] * o16[c];
        n1 = sqrtf(n1 + 1e-8f);
        n2 = sqrtf(n2 + 1e-8f);
        float* fh = fr + h * 312;
#pragma unroll
        for (int c = 0; c < 16; c++) {
            fh[168 + p * 16 + c] = o16[c];
            ogf[t][c] = o16[c];
        }
        fh[296 + p * 2] = n1;
        fh[296 + p * 2 + 1] = n2;
    }
    __syncthreads();
    // g_out = W_geo @ o_gf
    if (t < 128) {
        int o = t >> 4, c = t & 15;
        float acc = 0.f;
#pragma unroll 16
        for (int k = 0; k < 64; k++) acc += W_geo[o * 64 + k] * ogf[k][c];
        out_g[i * 128 + o * 16 + c] = acc;
    }
}

// -------------------- launch --------------------
extern "C" void kernel_launch(void* const* d_in, const int* in_sizes, int n_in,
                              void* d_out, int out_size) {
    const float* s    = (const float*)d_in[0];
    const float* g    = (const float*)d_in[1];
    const float* z    = (const float*)d_in[2];
    const float* T    = (const float*)d_in[3];
    const float* W_q  = (const float*)d_in[5];
    const float* b_q  = (const float*)d_in[6];
    const float* W_kv = (const float*)d_in[7];
    const float* b_kv = (const float*)d_in[8];
    const float* W_qp = (const float*)d_in[9];
    const float* b_qp = (const float*)d_in[10];
    const float* W_kp = (const float*)d_in[11];
    const float* b_kp = (const float*)d_in[12];
    const float* W_vg = (const float*)d_in[13];
    const float* b_vg = (const float*)d_in[14];
    const float* W_mg = (const float*)d_in[15];
    const float* W_b  = (const float*)d_in[16];
    const float* b_b  = (const float*)d_in[17];
    const float* W_dz = (const float*)d_in[18];
    const float* b_dz = (const float*)d_in[19];
    const float* hwr  = (const float*)d_in[20];
    const float* swr  = (const float*)d_in[21];
    const float* W_out = (const float*)d_in[22];
    const float* b_out = (const float*)d_in[23];
    const float* W_geo = (const float*)d_in[24];
    float* out = (float*)d_out;

    float *p_q, *p_kv, *p_qpl, *p_kpl, *p_vgl, *p_qe, *p_ke, *p_logits, *p_vcat, *p_oall, *p_feats, *p_part;
    cudaGetSymbolAddress((void**)&p_q, d_q);
    cudaGetSymbolAddress((void**)&p_kv, d_kv);
    cudaGetSymbolAddress((void**)&p_qpl, d_qpl);
    cudaGetSymbolAddress((void**)&p_kpl, d_kpl);
    cudaGetSymbolAddress((void**)&p_vgl, d_vgl);
    cudaGetSymbolAddress((void**)&p_qe, d_qe);
    cudaGetSymbolAddress((void**)&p_ke, d_ke);
    cudaGetSymbolAddress((void**)&p_logits, d_logits);
    cudaGetSymbolAddress((void**)&p_vcat, d_vcat);
    cudaGetSymbolAddress((void**)&p_oall, d_oall);
    cudaGetSymbolAddress((void**)&p_feats, d_feats);
    cudaGetSymbolAddress((void**)&p_part, d_part);

    // 1. frames
    k_frames<<<1, 512>>>(T, hwr);
    // 2. projections
    gemm_nn<<<dim3(16, 8, 1), 256>>>(s, W_q, p_q, b_q, 384, 384, 1024, 1024, 0, 0, 0);
    gemm_nn<<<dim3(32, 8, 1), 256>>>(s, W_kv, p_kv, b_kv, 384, 384, 2048, 2048, 0, 0, 0);
    gemm_nn<<<dim3(3, 8, 1), 256>>>(s, W_qp, p_qpl, b_qp, 384, 384, 192, 192, 0, 0, 0);
    gemm_nn<<<dim3(3, 8, 1), 256>>>(s, W_kp, p_kpl, b_kp, 384, 384, 192, 192, 0, 0, 0);
    gemm_nn<<<dim3(2, 8, 1), 256>>>(s, W_vg, p_vgl, b_vg, 384, 384, 128, 128, 0, 0, 0);
    // 3. points / extended feats / vcat
    k_points<<<512, 64>>>(g, W_mg);
    // 4. logits = qk*S1 + pt  (batched over h, K=160)
    gemm_nt<<<dim3(8, 8, 8), 256>>>(p_qe, p_ke, p_logits, 160, 160, 160, 512, 81920, 81920, 262144);
    // 5. add z-bias
    k_zbias<<<512, 256>>>(z, W_b, b_b);
    // 6. softmax
    k_softmax<<<dim3(512, 8), 256>>>(swr);
    // 7. apply: o | o_g in one batched GEMM (N=256)
    gemm_nn<<<dim3(4, 8, 8), 256>>>(p_logits, p_vcat, p_oall, nullptr, 512, 512, 2048, 2048,
                                    262144, 256, 256);
    // 8. za, o_rel
    k_za<<<512, 128>>>(z);
    k_orel<<<512, 64>>>();
    // 9. epilogue: transforms, norms, feats, g_out
    k_epilogue<<<512, 256>>>(W_dz, b_dz, W_geo, out + 196608);
    // 10. s_out = feats @ W_out + b_out (split-K=4, deterministic reduce)
    gemm_skp<<<dim3(6, 8, 4), 256>>>(p_feats, W_out, p_part, 624, 2496, 384, 384);
    k_red<<<768, 256>>>(b_out, out);
}

// round 15
// speedup vs baseline: 1.3060x; 1.3060x over previous
#include <cuda_runtime.h>
#include <math.h>

// B=1, N=512, CS=384, CZ=128, H=8, C=128, PQ=8, PV=8
// feats per head = 32(o_pair)+128(o)+8(o_rel)+128(o_g)+16(norms) = 312; CAT=2496
// out = [s_out 512*384][g_out 512*128]

#define S1 0.05103103630798287f           // sqrt(1/384)
#define S2 0.57735026918962576f           // sqrt(1/3)
#define HWS 0.09622504486493763f          // sqrt(1/108)

// -------------------- scratch (device globals, no allocs) --------------------
__device__ float d_Wall[384 * 3584];
__device__ float d_ball[3584];
__device__ float d_proj[512 * 3584];   // [n][ q(1024) | kv(2048) | qp(192) | kp(192) | vg(128) ]
__device__ float d_qn[512 * 4];
__device__ float d_tr[512 * 3];
__device__ float d_hw[8];
__device__ float d_qe[8 * 512 * 160];
__device__ float d_ke[8 * 512 * 160];
__device__ float d_logits[8 * 512 * 512];
__device__ float d_vcat[512 * 2048];   // [j][h][v(128) | vgg(128)]
__device__ float d_oall[512 * 2048];   // [i][h][o(128) | og(128)]
__device__ float d_za[512 * 1024];     // [i][h][128]
__device__ float d_orel[512 * 64];     // [i][h*8+c]
__device__ float d_feats[512 * 2496];
__device__ float d_part[4 * 512 * 384];

// -------------------- helpers --------------------
__device__ __forceinline__ void qrot(float qw, float qx, float qy, float qz,
                                     float vx, float vy, float vz,
                                     float& ox, float& oy, float& oz) {
    float ux = qy * vz - qz * vy;
    float uy = qz * vx - qx * vz;
    float uz = qx * vy - qy * vx;
    float wx = qy * uz - qz * uy;
    float wy = qz * ux - qx * uz;
    float wz = qx * uy - qy * ux;
    ox = vx + 2.f * (qw * ux + wx);
    oy = vy + 2.f * (qw * uy + wy);
    oz = vz + 2.f * (qw * uz + wz);
}

__device__ __forceinline__ void mm16(float (&acc)[4][4],
                                     const float (*As)[68], const float (*Bs)[68],
                                     int ty, int tx) {
#pragma unroll
    for (int k = 0; k < 16; k++) {
        const float4 av = *(const float4*)&As[k][ty * 4];
        const float4 bv = *(const float4*)&Bs[k][tx * 4];
        acc[0][0] += av.x * bv.x; acc[0][1] += av.x * bv.y; acc[0][2] += av.x * bv.z; acc[0][3] += av.x * bv.w;
        acc[1][0] += av.y * bv.x; acc[1][1] += av.y * bv.y; acc[1][2] += av.y * bv.z; acc[1][3] += av.y * bv.w;
        acc[2][0] += av.z * bv.x; acc[2][1] += av.z * bv.y; acc[2][2] += av.z * bv.z; acc[2][3] += av.z * bv.w;
        acc[3][0] += av.w * bv.x; acc[3][1] += av.w * bv.y; acc[3][2] += av.w * bv.z; acc[3][3] += av.w * bv.w;
    }
}

// -------------------- K: frames --------------------
__global__ void k_frames(const float* __restrict__ T, const float* __restrict__ hwr) {
    int n = threadIdx.x;
    const float* t = T + n * 16;
    float a = t[0], b = t[1], c = t[2], d = t[3];
    float inv = 1.0f / sqrtf(a * a + b * b + c * c + d * d + 1e-8f);
    d_qn[n * 4 + 0] = a * inv;
    d_qn[n * 4 + 1] = b * inv;
    d_qn[n * 4 + 2] = c * inv;
    d_qn[n * 4 + 3] = d * inv;
    d_tr[n * 3 + 0] = t[4];
    d_tr[n * 3 + 1] = t[5];
    d_tr[n * 3 + 2] = t[6];
    if (n < 8) {
        float x = hwr[n];
        float sp = (x > 20.f) ? x : log1pf(expf(x));
        d_hw[n] = sp * HWS;
    }
}

// -------------------- K: pack projection weights --------------------
__global__ void k_pack(const float* __restrict__ W_q, const float* __restrict__ b_q,
                       const float* __restrict__ W_kv, const float* __restrict__ b_kv,
                       const float* __restrict__ W_qp, const float* __restrict__ b_qp,
                       const float* __restrict__ W_kp, const float* __restrict__ b_kp,
                       const float* __restrict__ W_vg, const float* __restrict__ b_vg) {
    int gid = blockIdx.x * 256 + threadIdx.x;
    if (gid < 384 * 3584) {
        int k = gid / 3584, c = gid % 3584;
        float v;
        if (c < 1024)      v = W_q[k * 1024 + c];
        else if (c < 3072) v = W_kv[k * 2048 + c - 1024];
        else if (c < 3264) v = W_qp[k * 192 + c - 3072];
        else if (c < 3456) v = W_kp[k * 192 + c - 3264];
        else               v = W_vg[k * 128 + c - 3456];
        d_Wall[gid] = v;
    }
    if (gid < 3584) {
        int c = gid;
        float v;
        if (c < 1024)      v = b_q[c];
        else if (c < 3072) v = b_kv[c - 1024];
        else if (c < 3264) v = b_qp[c - 3072];
        else if (c < 3456) v = b_kp[c - 3264];
        else               v = b_vg[c - 3456];
        d_ball[c] = v;
    }
}

// -------------------- double-buffered tiled GEMM (64x64x16; M,N mult64; K mult16) ----
// BT=false: C[m,n] = sum_k A[m,k]*B[k,n];  BT=true: B indexed [n,k]
template <bool BT>
__global__ void __launch_bounds__(256) gemm2(
    const float* __restrict__ A, const float* __restrict__ B, float* __restrict__ C,
    const float* __restrict__ bias, int K, int k0z,
    int lda, int ldb, int ldc, long sA, long sB, long sC) {
    __shared__ float As[2][16][68];
    __shared__ float Bs[2][16][68];
    int tid = threadIdx.x;
    int tx = tid & 15, ty = tid >> 4;
    int mBase = blockIdx.y * 64, nBase = blockIdx.x * 64;
    A += (long)blockIdx.z * sA;
    B += (long)blockIdx.z * sB;
    C += (long)blockIdx.z * sC;
    int k0 = blockIdx.z * k0z;
    int a_m = tid >> 2, a_k = (tid & 3) * 4;
    int b_row = tid >> 4, b_c4 = (tid & 15) * 4;
    const float* Ap = A + (long)(mBase + a_m) * lda + k0 + a_k;
    const float* Bp = BT ? (B + (long)(nBase + a_m) * ldb + k0 + a_k)
                         : (B + (long)(k0 + b_row) * ldb + nBase + b_c4);
    long bstep = BT ? 16 : (long)16 * ldb;
    float acc[4][4] = {};
    int nT = K / 16;

    float4 ra = *(const float4*)Ap;
    float4 rb = *(const float4*)Bp;
    As[0][a_k + 0][a_m] = ra.x; As[0][a_k + 1][a_m] = ra.y;
    As[0][a_k + 2][a_m] = ra.z; As[0][a_k + 3][a_m] = ra.w;
    if (BT) {
        Bs[0][a_k + 0][a_m] = rb.x; Bs[0][a_k + 1][a_m] = rb.y;
        Bs[0][a_k + 2][a_m] = rb.z; Bs[0][a_k + 3][a_m] = rb.w;
    } else {
        *(float4*)&Bs[0][b_row][b_c4] = rb;
    }
    __syncthreads();

    for (int t = 0; t < nT; t++) {
        int cur = t & 1, nxt = cur ^ 1;
        bool more = (t + 1 < nT);
        if (more) {
            ra = *(const float4*)(Ap + (t + 1) * 16);
            rb = *(const float4*)(Bp + (t + 1) * bstep);
        }
        mm16(acc, As[cur], Bs[cur], ty, tx);
        if (more) {
            As[nxt][a_k + 0][a_m] = ra.x; As[nxt][a_k + 1][a_m] = ra.y;
            As[nxt][a_k + 2][a_m] = ra.z; As[nxt][a_k + 3][a_m] = ra.w;
            if (BT) {
                Bs[nxt][a_k + 0][a_m] = rb.x; Bs[nxt][a_k + 1][a_m] = rb.y;
                Bs[nxt][a_k + 2][a_m] = rb.z; Bs[nxt][a_k + 3][a_m] = rb.w;
            } else {
                *(float4*)&Bs[nxt][b_row][b_c4] = rb;
            }
        }
        __syncthreads();
    }

#pragma unroll
    for (int i2 = 0; i2 < 4; i2++) {
        long r = mBase + ty * 4 + i2;
        float4 v = make_float4(acc[i2][0], acc[i2][1], acc[i2][2], acc[i2][3]);
        if (bias) {
            float4 bv = *(const float4*)&bias[nBase + tx * 4];
            v.x += bv.x; v.y += bv.y; v.z += bv.z; v.w += bv.w;
        }
        *(float4*)&C[r * ldc + nBase + tx * 4] = v;
    }
}

__global__ void k_red(const float* __restrict__ b_out, float* __restrict__ out) {
    int idx = blockIdx.x * 256 + threadIdx.x;
    if (idx < 196608) {
        float v = d_part[idx] + d_part[196608 + idx] + d_part[2 * 196608 + idx] + d_part[3 * 196608 + idx];
        out[idx] = v + b_out[idx % 384];
    }
}

// -------------------- K: points + extended features + vcat --------------------
__global__ void k_points(const float* __restrict__ g, const float* __restrict__ W_mg) {
    __shared__ float wmg[1024];
    __shared__ float vgl[128], gsm[128];
    __shared__ float qf[4], tf[3], hws[8];
    __shared__ float qsq[64], ksq[64];
    int j = blockIdx.x;
    int t = threadIdx.x;  // 64 threads
    const float* pr = d_proj + (long)j * 3584;
    for (int idx = t; idx < 1024; idx += 64) wmg[idx] = W_mg[idx];
    for (int idx = t; idx < 128; idx += 64) {
        vgl[idx] = pr[3456 + idx];
        gsm[idx] = g[j * 128 + idx];
    }
    if (t < 4) qf[t] = d_qn[j * 4 + t];
    if (t < 3) tf[t] = d_tr[j * 3 + t];
    if (t < 8) hws[t] = d_hw[t];
    __syncthreads();
    float qw = qf[0], qx = qf[1], qy = qf[2], qz = qf[3];
    float tx0 = tf[0], ty0 = tf[1], tz0 = tf[2];
    int h = t >> 3, p = t & 7;
    float hw = hws[h];

    // q point
    {
        float px = pr[3072 + t], py = pr[3072 + 64 + t], pz = pr[3072 + 128 + t];
        float ax, ay, az;
        qrot(qw, qx, qy, qz, px, py, pz, ax, ay, az);
        ax += tx0; ay += ty0; az += tz0;
        qsq[t] = ax * ax + ay * ay + az * az;
        float* qe = d_qe + (h * 512 + j) * 160;
        qe[128 + p * 3 + 0] = ax * hw;
        qe[128 + p * 3 + 1] = ay * hw;
        qe[128 + p * 3 + 2] = az * hw;
    }
    // k point
    {
        float px = pr[3264 + t], py = pr[3264 + 64 + t], pz = pr[3264 + 128 + t];
        float bx, by, bz;
        qrot(qw, qx, qy, qz, px, py, pz, bx, by, bz);
        bx += tx0; by += ty0; bz += tz0;
        ksq[t] = bx * bx + by * by + bz * bz;
        float* ke = d_ke + (h * 512 + j) * 160;
        ke[128 + p * 3 + 0] = bx;
        ke[128 + p * 3 + 1] = by;
        ke[128 + p * 3 + 2] = bz;
    }
    // channel copies: qe[0:128]=q*S1, ke[0:128]=k, vcat v half
    for (int idx = t; idx < 1024; idx += 64) {
        int h2 = idx >> 7, c = idx & 127;
        d_qe[(h2 * 512 + j) * 160 + c] = pr[idx] * S1;
        d_ke[(h2 * 512 + j) * 160 + c] = pr[1024 + h2 * 256 + c];
        d_vcat[j * 2048 + h2 * 256 + c] = pr[1024 + h2 * 256 + 128 + c];
    }
    // vgg: multivector mix + forward transform
    float mv[16];
#pragma unroll
    for (int c = 0; c < 16; c++) {
        float acc = 0.f;
#pragma unroll
        for (int ii = 0; ii < 8; ii++) acc += wmg[t * 16 + ii] * vgl[ii * 16 + c];
#pragma unroll
        for (int ii = 0; ii < 8; ii++) acc += wmg[t * 16 + 8 + ii] * gsm[ii * 16 + c];
        mv[c] = acc;
    }
    float o16[16];
    o16[0] = mv[0];
    qrot(qw, qx, qy, qz, mv[1], mv[2], mv[3], o16[1], o16[2], o16[3]);
    qrot(qw, qx, qy, qz, mv[4], mv[5], mv[6], o16[4], o16[5], o16[6]);
    {
        float w10 = mv[10];
        float rx, ry, rz;
        qrot(qw, qx, qy, qz, mv[7], mv[8], mv[9], rx, ry, rz);
        o16[7] = rx + w10 * tx0;
        o16[8] = ry + w10 * ty0;
        o16[9] = rz + w10 * tz0;
    }
#pragma unroll
    for (int c = 10; c < 16; c++) o16[c] = mv[c];
    float* vdst = d_vcat + j * 2048 + h * 256 + 128 + p * 16;
#pragma unroll
    for (int c = 0; c < 16; c++) vdst[c] = o16[c];

    __syncthreads();
    if (p == 0) {
        float qs = 0.f, ks = 0.f;
#pragma unroll
        for (int pp = 0; pp < 8; pp++) { qs += qsq[h * 8 + pp]; ks += ksq[h * 8 + pp]; }
        float* qe0 = d_qe + (h * 512 + j) * 160;
        float* ke0 = d_ke + (h * 512 + j) * 160;
        qe0[152] = -0.5f * hw * qs; qe0[153] = 1.f;
        ke0[152] = 1.f;             ke0[153] = -0.5f * hw * ks;
#pragma unroll
        for (int c = 154; c < 160; c++) { qe0[c] = 0.f; ke0[c] = 0.f; }
    }
}

// -------------------- K: z bias add into logits --------------------
__global__ void __launch_bounds__(256) k_zbias(const float* __restrict__ z,
                                               const float* __restrict__ W_b,
                                               const float* __restrict__ b_b) {
    int i = blockIdx.x;
    int t = threadIdx.x;
    int w = t >> 5, l = t & 31;
    int c0 = l * 4;
    float wreg[4][8];
#pragma unroll
    for (int k = 0; k < 4; k++)
#pragma unroll
        for (int h = 0; h < 8; h++) wreg[k][h] = W_b[(c0 + k) * 8 + h];
    float bb[8];
#pragma unroll
    for (int h = 0; h < 8; h++) bb[h] = b_b[h];

    for (int j = w; j < 512; j += 8) {
        const float4 zv = *(const float4*)(z + ((long)(i * 512 + j)) * 128 + c0);
        float acc[8];
#pragma unroll
        for (int h = 0; h < 8; h++)
            acc[h] = zv.x * wreg[0][h] + zv.y * wreg[1][h] + zv.z * wreg[2][h] + zv.w * wreg[3][h];
#pragma unroll
        for (int off = 16; off > 0; off >>= 1)
#pragma unroll
            for (int h = 0; h < 8; h++) acc[h] += __shfl_xor_sync(0xffffffffu, acc[h], off);
        if (l == 0) {
#pragma unroll
            for (int h = 0; h < 8; h++)
                d_logits[h * 262144 + i * 512 + j] += S2 * (acc[h] + bb[h]);
        }
    }
}

// -------------------- K: softmax rows --------------------
__global__ void k_softmax(const float* __restrict__ sw_) {
    __shared__ float red[256];
    int i = blockIdx.x, h = blockIdx.y, t = threadIdx.x;
    float sw = sw_[h];
    float* row = d_logits + h * 262144 + i * 512;
    float v0 = sw * row[t], v1 = sw * row[t + 256];
    float m = fmaxf(v0, v1);
    red[t] = m;
    __syncthreads();
    for (int s = 128; s > 0; s >>= 1) {
        if (t < s) red[t] = fmaxf(red[t], red[t + s]);
        __syncthreads();
    }
    m = red[0];
    __syncthreads();
    float e0 = expf(v0 - m), e1 = expf(v1 - m);
    red[t] = e0 + e1;
    __syncthreads();
    for (int s = 128; s > 0; s >>= 1) {
        if (t < s) red[t] += red[t + s];
        __syncthreads();
    }
    float inv = 1.f / red[0];
    row[t] = e0 * inv;
    row[t + 256] = e1 * inv;
}

// -------------------- K: za = sum_j a*z --------------------
__global__ void __launch_bounds__(128) k_za(const float* __restrict__ z) {
    __shared__ float a_s[4096];
    int i = blockIdx.x, t = threadIdx.x;  // 128
    for (int idx = t; idx < 4096; idx += 128) {
        int h = idx >> 9, j = idx & 511;
        a_s[idx] = d_logits[h * 262144 + i * 512 + j];
    }
    __syncthreads();
    float acc[8] = {};
    const float* zp = z + (long)i * 65536 + t;
    for (int j = 0; j < 512; j++) {
        float zv = zp[(long)j * 128];
#pragma unroll
        for (int h = 0; h < 8; h++) acc[h] += a_s[h * 512 + j] * zv;
    }
#pragma unroll
    for (int h = 0; h < 8; h++) d_za[i * 1024 + h * 128 + t] = acc[h];
}

// -------------------- K: o_rel (rel computed on the fly) --------------------
__global__ void __launch_bounds__(64) k_orel() {
    __shared__ float a_s[4096];
    __shared__ float rel_s[64][9];
    __shared__ float qf[4], tf[3];
    int i = blockIdx.x, t = threadIdx.x;  // 64
    if (t < 4) qf[t] = d_qn[i * 4 + t];
    if (t < 3) tf[t] = d_tr[i * 3 + t];
    for (int idx = t; idx < 4096; idx += 64) {
        int h = idx >> 9, j = idx & 511;
        a_s[idx] = d_logits[h * 262144 + i * 512 + j];
    }
    __syncthreads();
    float wi = qf[0], xi = qf[1], yi = qf[2], zi = qf[3];
    float aw = wi, ax = -xi, ay = -yi, az = -zi;  // conj
    int h = t >> 3, c = t & 7;
    float acc = 0.f;
    for (int tile = 0; tile < 8; tile++) {
        int j = tile * 64 + t;
        float bw = d_qn[j * 4], bx = d_qn[j * 4 + 1], by = d_qn[j * 4 + 2], bz = d_qn[j * 4 + 3];
        rel_s[t][0] = aw * bw - ax * bx - ay * by - az * bz;
        rel_s[t][1] = aw * bx + ax * bw + ay * bz - az * by;
        rel_s[t][2] = aw * by - ax * bz + ay * bw + az * bx;
        rel_s[t][3] = aw * bz + ax * by - ay * bx + az * bw;
        float dx = d_tr[j * 3] - tf[0], dy = d_tr[j * 3 + 1] - tf[1], dz2 = d_tr[j * 3 + 2] - tf[2];
        float rx, ry, rz;
        qrot(aw, ax, ay, az, dx, dy, dz2, rx, ry, rz);
        rel_s[t][4] = rx; rel_s[t][5] = ry; rel_s[t][6] = rz; rel_s[t][7] = 0.f;
        __syncthreads();
        const float* ah = a_s + h * 512 + tile * 64;
#pragma unroll 16
        for (int jj = 0; jj < 64; jj++) acc += ah[jj] * rel_s[jj][c];
        __syncthreads();
    }
    d_orel[i * 64 + t] = acc;
}

// -------------------- K: epilogue (inv transform, norms, feats, g_out) --------------------
__global__ void __launch_bounds__(256) k_epilogue(const float* __restrict__ W_dz,
                                                  const float* __restrict__ b_dz,
                                                  const float* __restrict__ W_geo,
                                                  float* __restrict__ out_g) {
    __shared__ float ogf[64][17];
    __shared__ float qf[4], tf[3];
    int i = blockIdx.x, t = threadIdx.x;  // 256
    if (t < 4) qf[t] = d_qn[i * 4 + t];
    if (t < 3) tf[t] = d_tr[i * 3 + t];
    __syncthreads();
    float* fr = d_feats + i * 2496;

    // o_pair = za @ W_dz + b_dz
    {
        int h = t >> 5, oc = t & 31;
        const float* za = d_za + i * 1024 + h * 128;
        float acc = b_dz[oc];
#pragma unroll 8
        for (int c = 0; c < 128; c++) acc += za[c] * W_dz[c * 32 + oc];
        fr[h * 312 + oc] = acc;
    }
    // o copy
    for (int idx = t; idx < 1024; idx += 256) {
        int h = idx >> 7, c = idx & 127;
        fr[h * 312 + 32 + c] = d_oall[i * 2048 + h * 256 + c];
    }
    // o_rel copy
    if (t < 64) fr[(t >> 3) * 312 + 160 + (t & 7)] = d_orel[i * 64 + t];
    // o_g inverse transform + norms
    if (t < 64) {
        int h = t >> 3, p = t & 7;
        float qw = qf[0], qx = -qf[1], qy = -qf[2], qz = -qf[3];  // conj
        const float* src = d_oall + i * 2048 + h * 256 + 128 + p * 16;
        float mv[16];
#pragma unroll
        for (int c = 0; c < 16; c++) mv[c] = src[c];
        float o16[16];
        o16[0] = mv[0];
        qrot(qw, qx, qy, qz, mv[1], mv[2], mv[3], o16[1], o16[2], o16[3]);
        qrot(qw, qx, qy, qz, mv[4], mv[5], mv[6], o16[4], o16[5], o16[6]);
        {
            float w10 = mv[10];
            qrot(qw, qx, qy, qz, mv[7] - w10 * tf[0], mv[8] - w10 * tf[1], mv[9] - w10 * tf[2],
                 o16[7], o16[8], o16[9]);
        }
#pragma unroll
        for (int c = 10; c < 16; c++) o16[c] = mv[c];
        float n1 = 0.f, n2 = 0.f;
#pragma unroll
        for (int c = 0; c < 10; c++) n1 += o16[c] * o16[c];
#pragma unroll
        for (int c = 10; c < 16; c++) n2 += o16[c] * o16[c];
        n1 = sqrtf(n1 + 1e-8f);
        n2 = sqrtf(n2 + 1e-8f);
        float* fh = fr + h * 312;
#pragma unroll
        for (int c = 0; c < 16; c++) {
            fh[168 + p * 16 + c] = o16[c];
            ogf[t][c] = o16[c];
        }
        fh[296 + p * 2] = n1;
        fh[296 + p * 2 + 1] = n2;
    }
    __syncthreads();
    // g_out = W_geo @ o_gf
    if (t < 128) {
        int o = t >> 4, c = t & 15;
        float acc = 0.f;
#pragma unroll 16
        for (int k = 0; k < 64; k++) acc += W_geo[o * 64 + k] * ogf[k][c];
        out_g[i * 128 + o * 16 + c] = acc;
    }
}

// -------------------- launch --------------------
extern "C" void kernel_launch(void* const* d_in, const int* in_sizes, int n_in,
                              void* d_out, int out_size) {
    const float* s    = (const float*)d_in[0];
    const float* g    = (const float*)d_in[1];
    const float* z    = (const float*)d_in[2];
    const float* T    = (const float*)d_in[3];
    const float* W_q  = (const float*)d_in[5];
    const float* b_q  = (const float*)d_in[6];
    const float* W_kv = (const float*)d_in[7];
    const float* b_kv = (const float*)d_in[8];
    const float* W_qp = (const float*)d_in[9];
    const float* b_qp = (const float*)d_in[10];
    const float* W_kp = (const float*)d_in[11];
    const float* b_kp = (const float*)d_in[12];
    const float* W_vg = (const float*)d_in[13];
    const float* b_vg = (const float*)d_in[14];
    const float* W_mg = (const float*)d_in[15];
    const float* W_b  = (const float*)d_in[16];
    const float* b_b  = (const float*)d_in[17];
    const float* W_dz = (const float*)d_in[18];
    const float* b_dz = (const float*)d_in[19];
    const float* hwr  = (const float*)d_in[20];
    const float* swr  = (const float*)d_in[21];
    const float* W_out = (const float*)d_in[22];
    const float* b_out = (const float*)d_in[23];
    const float* W_geo = (const float*)d_in[24];
    float* out = (float*)d_out;

    float *p_Wall, *p_ball, *p_proj, *p_qe, *p_ke, *p_logits, *p_vcat, *p_oall, *p_feats, *p_part;
    cudaGetSymbolAddress((void**)&p_Wall, d_Wall);
    cudaGetSymbolAddress((void**)&p_ball, d_ball);
    cudaGetSymbolAddress((void**)&p_proj, d_proj);
    cudaGetSymbolAddress((void**)&p_qe, d_qe);
    cudaGetSymbolAddress((void**)&p_ke, d_ke);
    cudaGetSymbolAddress((void**)&p_logits, d_logits);
    cudaGetSymbolAddress((void**)&p_vcat, d_vcat);
    cudaGetSymbolAddress((void**)&p_oall, d_oall);
    cudaGetSymbolAddress((void**)&p_feats, d_feats);
    cudaGetSymbolAddress((void**)&p_part, d_part);

    // 1. frames + weight packing
    k_frames<<<1, 512>>>(T, hwr);
    k_pack<<<(384 * 3584 + 255) / 256, 256>>>(W_q, b_q, W_kv, b_kv, W_qp, b_qp, W_kp, b_kp, W_vg, b_vg);
    // 2. all projections in ONE GEMM: [512,3584] = s @ Wall + ball
    gemm2<false><<<dim3(56, 8, 1), 256>>>(s, p_Wall, p_proj, p_ball, 384, 0,
                                          384, 3584, 3584, 0, 0, 0);
    // 3. points / extended feats / vcat
    k_points<<<512, 64>>>(g, W_mg);
    // 4. logits = qk*S1 + pt (batched over h, K=160, B transposed)
    gemm2<true><<<dim3(8, 8, 8), 256>>>(p_qe, p_ke, p_logits, nullptr, 160, 0,
                                        160, 160, 512, 81920, 81920, 262144);
    // 5. add z-bias
    k_zbias<<<512, 256>>>(z, W_b, b_b);
    // 6. softmax
    k_softmax<<<dim3(512, 8), 256>>>(swr);
    // 7. apply: o | o_g in one batched GEMM (N=256 per head)
    gemm2<false><<<dim3(4, 8, 8), 256>>>(p_logits, p_vcat, p_oall, nullptr, 512, 0,
                                         512, 2048, 2048, 262144, 256, 256);
    // 8. za, o_rel
    k_za<<<512, 128>>>(z);
    k_orel<<<512, 64>>>();
    // 9. epilogue: transforms, norms, feats, g_out
    k_epilogue<<<512, 256>>>(W_dz, b_dz, W_geo, out + 196608);
    // 10. s_out = feats @ W_out (split-K=4 partials, deterministic reduce)
    gemm2<false><<<dim3(6, 8, 4), 256>>>(p_feats, W_out, p_part, nullptr, 624, 624,
                                         2496, 384, 384, 0, 0, 196608);
    k_red<<<768, 256>>>(b_out, out);
}

// round 16
// speedup vs baseline: 1.4579x; 1.1163x over previous
#include <cuda_runtime.h>
#include <math.h>

// B=1, N=512, CS=384, CZ=128, H=8, C=128, PQ=8, PV=8
// feats per head = 32(o_pair)+128(o)+8(o_rel)+128(o_g)+16(norms) = 312; CAT=2496
// out = [s_out 512*384][g_out 512*128]

#define S1 0.05103103630798287f           // sqrt(1/384)
#define S2 0.57735026918962576f           // sqrt(1/3)
#define HWS 0.09622504486493763f          // sqrt(1/108)

// -------------------- scratch (device globals, no allocs) --------------------
__device__ float d_Wall[384 * 3584];
__device__ float d_ball[3584];
__device__ float d_proj[512 * 3584];   // [n][ q(1024) | kv(2048) | qp(192) | kp(192) | vg(128) ]
__device__ float d_qn[512 * 4];
__device__ float d_tr[512 * 3];
__device__ float d_hw[8];
__device__ float d_qe[8 * 512 * 160];
__device__ float d_ke[8 * 512 * 160];
__device__ float d_logits[8 * 512 * 512];
__device__ float d_vcat[512 * 2048];   // [j][h][v(128) | vgg(128)]
__device__ float d_oall[512 * 2048];   // [i][h][o(128) | og(128)]
__device__ float d_za[512 * 1024];     // [i][h][128]
__device__ float d_orel[512 * 64];     // [i][h*8+c]
__device__ float d_feats[512 * 2496];
__device__ float d_part[4 * 512 * 384];

// -------------------- helpers --------------------
__device__ __forceinline__ void qrot(float qw, float qx, float qy, float qz,
                                     float vx, float vy, float vz,
                                     float& ox, float& oy, float& oz) {
    float ux = qy * vz - qz * vy;
    float uy = qz * vx - qx * vz;
    float uz = qx * vy - qy * vx;
    float wx = qy * uz - qz * uy;
    float wy = qz * ux - qx * uz;
    float wz = qx * uy - qy * ux;
    ox = vx + 2.f * (qw * ux + wx);
    oy = vy + 2.f * (qw * uy + wy);
    oz = vz + 2.f * (qw * uz + wz);
}

__device__ __forceinline__ void mm16(float (&acc)[4][4],
                                     const float (*As)[68], const float (*Bs)[68],
                                     int ty, int tx) {
#pragma unroll
    for (int k = 0; k < 16; k++) {
        const float4 av = *(const float4*)&As[k][ty * 4];
        const float4 bv = *(const float4*)&Bs[k][tx * 4];
        acc[0][0] += av.x * bv.x; acc[0][1] += av.x * bv.y; acc[0][2] += av.x * bv.z; acc[0][3] += av.x * bv.w;
        acc[1][0] += av.y * bv.x; acc[1][1] += av.y * bv.y; acc[1][2] += av.y * bv.z; acc[1][3] += av.y * bv.w;
        acc[2][0] += av.z * bv.x; acc[2][1] += av.z * bv.y; acc[2][2] += av.z * bv.z; acc[2][3] += av.z * bv.w;
        acc[3][0] += av.w * bv.x; acc[3][1] += av.w * bv.y; acc[3][2] += av.w * bv.z; acc[3][3] += av.w * bv.w;
    }
}

// -------------------- K: frames --------------------
__global__ void k_frames(const float* __restrict__ T, const float* __restrict__ hwr) {
    int n = threadIdx.x;
    const float* t = T + n * 16;
    float a = t[0], b = t[1], c = t[2], d = t[3];
    float inv = 1.0f / sqrtf(a * a + b * b + c * c + d * d + 1e-8f);
    d_qn[n * 4 + 0] = a * inv;
    d_qn[n * 4 + 1] = b * inv;
    d_qn[n * 4 + 2] = c * inv;
    d_qn[n * 4 + 3] = d * inv;
    d_tr[n * 3 + 0] = t[4];
    d_tr[n * 3 + 1] = t[5];
    d_tr[n * 3 + 2] = t[6];
    if (n < 8) {
        float x = hwr[n];
        float sp = (x > 20.f) ? x : log1pf(expf(x));
        d_hw[n] = sp * HWS;
    }
}

// -------------------- K: pack projection weights --------------------
__global__ void k_pack(const float* __restrict__ W_q, const float* __restrict__ b_q,
                       const float* __restrict__ W_kv, const float* __restrict__ b_kv,
                       const float* __restrict__ W_qp, const float* __restrict__ b_qp,
                       const float* __restrict__ W_kp, const float* __restrict__ b_kp,
                       const float* __restrict__ W_vg, const float* __restrict__ b_vg) {
    int gid = blockIdx.x * 256 + threadIdx.x;
    if (gid < 384 * 3584) {
        int k = gid / 3584, c = gid % 3584;
        float v;
        if (c < 1024)      v = W_q[k * 1024 + c];
        else if (c < 3072) v = W_kv[k * 2048 + c - 1024];
        else if (c < 3264) v = W_qp[k * 192 + c - 3072];
        else if (c < 3456) v = W_kp[k * 192 + c - 3264];
        else               v = W_vg[k * 128 + c - 3456];
        d_Wall[gid] = v;
    }
    if (gid < 3584) {
        int c = gid;
        float v;
        if (c < 1024)      v = b_q[c];
        else if (c < 3072) v = b_kv[c - 1024];
        else if (c < 3264) v = b_qp[c - 3072];
        else if (c < 3456) v = b_kp[c - 3264];
        else               v = b_vg[c - 3456];
        d_ball[c] = v;
    }
}

// -------------------- double-buffered tiled GEMM (64x64x16; M,N mult64; K mult16) ----
// BT=false: C[m,n] = sum_k A[m,k]*B[k,n];  BT=true: B indexed [n,k]
template <bool BT>
__global__ void __launch_bounds__(256) gemm2(
    const float* __restrict__ A, const float* __restrict__ B, float* __restrict__ C,
    const float* __restrict__ bias, int K, int k0z,
    int lda, int ldb, int ldc, long sA, long sB, long sC) {
    __shared__ float As[2][16][68];
    __shared__ float Bs[2][16][68];
    int tid = threadIdx.x;
    int tx = tid & 15, ty = tid >> 4;
    int mBase = blockIdx.y * 64, nBase = blockIdx.x * 64;
    A += (long)blockIdx.z * sA;
    B += (long)blockIdx.z * sB;
    C += (long)blockIdx.z * sC;
    int k0 = blockIdx.z * k0z;
    int a_m = tid >> 2, a_k = (tid & 3) * 4;
    int b_row = tid >> 4, b_c4 = (tid & 15) * 4;
    const float* Ap = A + (long)(mBase + a_m) * lda + k0 + a_k;
    const float* Bp = BT ? (B + (long)(nBase + a_m) * ldb + k0 + a_k)
                         : (B + (long)(k0 + b_row) * ldb + nBase + b_c4);
    long bstep = BT ? 16 : (long)16 * ldb;
    float acc[4][4] = {};
    int nT = K / 16;

    float4 ra = *(const float4*)Ap;
    float4 rb = *(const float4*)Bp;
    As[0][a_k + 0][a_m] = ra.x; As[0][a_k + 1][a_m] = ra.y;
    As[0][a_k + 2][a_m] = ra.z; As[0][a_k + 3][a_m] = ra.w;
    if (BT) {
        Bs[0][a_k + 0][a_m] = rb.x; Bs[0][a_k + 1][a_m] = rb.y;
        Bs[0][a_k + 2][a_m] = rb.z; Bs[0][a_k + 3][a_m] = rb.w;
    } else {
        *(float4*)&Bs[0][b_row][b_c4] = rb;
    }
    __syncthreads();

    for (int t = 0; t < nT; t++) {
        int cur = t & 1, nxt = cur ^ 1;
        bool more = (t + 1 < nT);
        if (more) {
            ra = *(const float4*)(Ap + (t + 1) * 16);
            rb = *(const float4*)(Bp + (t + 1) * bstep);
        }
        mm16(acc, As[cur], Bs[cur], ty, tx);
        if (more) {
            As[nxt][a_k + 0][a_m] = ra.x; As[nxt][a_k + 1][a_m] = ra.y;
            As[nxt][a_k + 2][a_m] = ra.z; As[nxt][a_k + 3][a_m] = ra.w;
            if (BT) {
                Bs[nxt][a_k + 0][a_m] = rb.x; Bs[nxt][a_k + 1][a_m] = rb.y;
                Bs[nxt][a_k + 2][a_m] = rb.z; Bs[nxt][a_k + 3][a_m] = rb.w;
            } else {
                *(float4*)&Bs[nxt][b_row][b_c4] = rb;
            }
        }
        __syncthreads();
    }

#pragma unroll
    for (int i2 = 0; i2 < 4; i2++) {
        long r = mBase + ty * 4 + i2;
        float4 v = make_float4(acc[i2][0], acc[i2][1], acc[i2][2], acc[i2][3]);
        if (bias) {
            float4 bv = *(const float4*)&bias[nBase + tx * 4];
            v.x += bv.x; v.y += bv.y; v.z += bv.z; v.w += bv.w;
        }
        *(float4*)&C[r * ldc + nBase + tx * 4] = v;
    }
}

__global__ void k_red(const float* __restrict__ b_out, float* __restrict__ out) {
    int idx = blockIdx.x * 256 + threadIdx.x;
    if (idx < 196608) {
        float v = d_part[idx] + d_part[196608 + idx] + d_part[2 * 196608 + idx] + d_part[3 * 196608 + idx];
        out[idx] = v + b_out[idx % 384];
    }
}

// -------------------- K: points + extended features + vcat (256 thr) --------------------
__global__ void __launch_bounds__(256) k_points(const float* __restrict__ g,
                                                const float* __restrict__ W_mg) {
    __shared__ float wmg[1024];
    __shared__ float vgl[128], gsm[128];
    __shared__ float qf[4], tf[3], hws[8];
    __shared__ float qsq[64], ksq[64];
    __shared__ float mvs[64][17];
    int j = blockIdx.x;
    int t = threadIdx.x;  // 256 threads
    const float* pr = d_proj + (long)j * 3584;

    // loads
    {
        const float4* w4 = (const float4*)W_mg;
        ((float4*)wmg)[t] = w4[t];
    }
    if (t < 32) {
        ((float4*)vgl)[t] = *(const float4*)(pr + 3456 + t * 4);
        ((float4*)gsm)[t] = *(const float4*)(g + j * 128 + t * 4);
    }
    if (t < 4) qf[t] = d_qn[j * 4 + t];
    if (t < 3) tf[t] = d_tr[j * 3 + t];
    if (t < 8) hws[t] = d_hw[t];
    __syncthreads();
    float qw = qf[0], qx = qf[1], qy = qf[2], qz = qf[3];
    float tx0 = tf[0], ty0 = tf[1], tz0 = tf[2];

    // vectorized channel copies: 256 float4 over 1024 channels
    {
        int c4 = t * 4;
        int h2 = c4 >> 7, c = c4 & 127;
        float4 qv = *(const float4*)(pr + c4);
        qv.x *= S1; qv.y *= S1; qv.z *= S1; qv.w *= S1;
        *(float4*)(d_qe + (long)(h2 * 512 + j) * 160 + c) = qv;
        float4 kvv = *(const float4*)(pr + 1024 + h2 * 256 + c);
        *(float4*)(d_ke + (long)(h2 * 512 + j) * 160 + c) = kvv;
        float4 vv = *(const float4*)(pr + 1024 + h2 * 256 + 128 + c);
        *(float4*)(d_vcat + (long)j * 2048 + h2 * 256 + c) = vv;
    }

    // q/k points (threads 0..63)
    if (t < 64) {
        int h = t >> 3, p = t & 7;
        float hw = hws[h];
        {
            float px = pr[3072 + t], py = pr[3072 + 64 + t], pz = pr[3072 + 128 + t];
            float ax, ay, az;
            qrot(qw, qx, qy, qz, px, py, pz, ax, ay, az);
            ax += tx0; ay += ty0; az += tz0;
            qsq[t] = ax * ax + ay * ay + az * az;
            float* qe = d_qe + (long)(h * 512 + j) * 160;
            qe[128 + p * 3 + 0] = ax * hw;
            qe[128 + p * 3 + 1] = ay * hw;
            qe[128 + p * 3 + 2] = az * hw;
        }
        {
            float px = pr[3264 + t], py = pr[3264 + 64 + t], pz = pr[3264 + 128 + t];
            float bx, by, bz;
            qrot(qw, qx, qy, qz, px, py, pz, bx, by, bz);
            bx += tx0; by += ty0; bz += tz0;
            ksq[t] = bx * bx + by * by + bz * bz;
            float* ke = d_ke + (long)(h * 512 + j) * 160;
            ke[128 + p * 3 + 0] = bx;
            ke[128 + p * 3 + 1] = by;
            ke[128 + p * 3 + 2] = bz;
        }
    }

    // vgg mix: 256 threads each compute 4 of the 64x16 outputs
    {
        int hp = t >> 2, cg = t & 3;
#pragma unroll
        for (int cc = 0; cc < 4; cc++) {
            int c = cg * 4 + cc;
            float acc = 0.f;
#pragma unroll
            for (int ii = 0; ii < 8; ii++) acc += wmg[hp * 16 + ii] * vgl[ii * 16 + c];
#pragma unroll
            for (int ii = 0; ii < 8; ii++) acc += wmg[hp * 16 + 8 + ii] * gsm[ii * 16 + c];
            mvs[hp][c] = acc;
        }
    }
    __syncthreads();

    if (t < 64) {
        int h = t >> 3, p = t & 7;
        float mv[16];
#pragma unroll
        for (int c = 0; c < 16; c++) mv[c] = mvs[t][c];
        float o16[16];
        o16[0] = mv[0];
        qrot(qw, qx, qy, qz, mv[1], mv[2], mv[3], o16[1], o16[2], o16[3]);
        qrot(qw, qx, qy, qz, mv[4], mv[5], mv[6], o16[4], o16[5], o16[6]);
        {
            float w10 = mv[10];
            float rx, ry, rz;
            qrot(qw, qx, qy, qz, mv[7], mv[8], mv[9], rx, ry, rz);
            o16[7] = rx + w10 * tx0;
            o16[8] = ry + w10 * ty0;
            o16[9] = rz + w10 * tz0;
        }
#pragma unroll
        for (int c = 10; c < 16; c++) o16[c] = mv[c];
        float* vdst = d_vcat + (long)j * 2048 + h * 256 + 128 + p * 16;
#pragma unroll
        for (int c4 = 0; c4 < 4; c4++)
            *(float4*)(vdst + c4 * 4) = make_float4(o16[c4 * 4], o16[c4 * 4 + 1],
                                                    o16[c4 * 4 + 2], o16[c4 * 4 + 3]);
        if (p == 0) {
            float hw = hws[h];
            float qs = 0.f, ks = 0.f;
#pragma unroll
            for (int pp = 0; pp < 8; pp++) { qs += qsq[h * 8 + pp]; ks += ksq[h * 8 + pp]; }
            float* qe0 = d_qe + (long)(h * 512 + j) * 160;
            float* ke0 = d_ke + (long)(h * 512 + j) * 160;
            qe0[152] = -0.5f * hw * qs; qe0[153] = 1.f;
            ke0[152] = 1.f;             ke0[153] = -0.5f * hw * ks;
#pragma unroll
            for (int c = 154; c < 160; c++) { qe0[c] = 0.f; ke0[c] = 0.f; }
        }
    }
}

// -------------------- K: z bias add into logits --------------------
__global__ void __launch_bounds__(256) k_zbias(const float* __restrict__ z,
                                               const float* __restrict__ W_b,
                                               const float* __restrict__ b_b) {
    int i = blockIdx.x;
    int t = threadIdx.x;
    int w = t >> 5, l = t & 31;
    int c0 = l * 4;
    float wreg[4][8];
#pragma unroll
    for (int k = 0; k < 4; k++)
#pragma unroll
        for (int h = 0; h < 8; h++) wreg[k][h] = W_b[(c0 + k) * 8 + h];
    float bb[8];
#pragma unroll
    for (int h = 0; h < 8; h++) bb[h] = b_b[h];

    for (int j = w; j < 512; j += 8) {
        const float4 zv = *(const float4*)(z + ((long)(i * 512 + j)) * 128 + c0);
        float acc[8];
#pragma unroll
        for (int h = 0; h < 8; h++)
            acc[h] = zv.x * wreg[0][h] + zv.y * wreg[1][h] + zv.z * wreg[2][h] + zv.w * wreg[3][h];
#pragma unroll
        for (int off = 16; off > 0; off >>= 1)
#pragma unroll
            for (int h = 0; h < 8; h++) acc[h] += __shfl_xor_sync(0xffffffffu, acc[h], off);
        if (l == 0) {
#pragma unroll
            for (int h = 0; h < 8; h++)
                d_logits[h * 262144 + i * 512 + j] += S2 * (acc[h] + bb[h]);
        }
    }
}

// -------------------- K: softmax rows --------------------
__global__ void k_softmax(const float* __restrict__ sw_) {
    __shared__ float red[256];
    int i = blockIdx.x, h = blockIdx.y, t = threadIdx.x;
    float sw = sw_[h];
    float* row = d_logits + h * 262144 + i * 512;
    float v0 = sw * row[t], v1 = sw * row[t + 256];
    float m = fmaxf(v0, v1);
    red[t] = m;
    __syncthreads();
    for (int s = 128; s > 0; s >>= 1) {
        if (t < s) red[t] = fmaxf(red[t], red[t + s]);
        __syncthreads();
    }
    m = red[0];
    __syncthreads();
    float e0 = expf(v0 - m), e1 = expf(v1 - m);
    red[t] = e0 + e1;
    __syncthreads();
    for (int s = 128; s > 0; s >>= 1) {
        if (t < s) red[t] += red[t + s];
        __syncthreads();
    }
    float inv = 1.f / red[0];
    row[t] = e0 * inv;
    row[t + 256] = e1 * inv;
}

// -------------------- K: za = sum_j a*z (256 thr, 2-way split, 4x unroll) --------------------
__global__ void __launch_bounds__(256) k_za(const float* __restrict__ z) {
    __shared__ float a_s[4096];
    __shared__ float part[2][1024];
    int i = blockIdx.x, t = threadIdx.x;  // 256
    for (int idx = t; idx < 4096; idx += 256) {
        int h = idx >> 9, j = idx & 511;
        a_s[idx] = d_logits[h * 262144 + i * 512 + j];
    }
    __syncthreads();
    int c = t & 127, half = t >> 7;
    const float* zp = z + (long)i * 65536 + (long)half * 256 * 128 + c;
    const float* ab = a_s + half * 256;
    float acc[8] = {};
    for (int j = 0; j < 256; j += 4) {
        float z0 = zp[(long)j * 128];
        float z1 = zp[(long)(j + 1) * 128];
        float z2 = zp[(long)(j + 2) * 128];
        float z3 = zp[(long)(j + 3) * 128];
#pragma unroll
        for (int h = 0; h < 8; h++) {
            const float* ar = ab + h * 512 + j;
            acc[h] += ar[0] * z0 + ar[1] * z1 + ar[2] * z2 + ar[3] * z3;
        }
    }
#pragma unroll
    for (int h = 0; h < 8; h++) part[half][h * 128 + c] = acc[h];
    __syncthreads();
    for (int idx = t; idx < 1024; idx += 256)
        d_za[i * 1024 + idx] = part[0][idx] + part[1][idx];
}

// -------------------- K: o_rel (256 thr, 4 groups x 2 tiles) --------------------
__global__ void __launch_bounds__(256) k_orel() {
    __shared__ float a_s[4096];
    __shared__ float rel_s[4][64][9];
    __shared__ float partial[4][64];
    __shared__ float qf[4], tf[3];
    int i = blockIdx.x, t = threadIdx.x;  // 256
    int gr = t >> 6, s = t & 63;
    if (t < 4) qf[t] = d_qn[i * 4 + t];
    if (t < 3) tf[t] = d_tr[i * 3 + t];
    for (int idx = t; idx < 4096; idx += 256) {
        int h = idx >> 9, j = idx & 511;
        a_s[idx] = d_logits[h * 262144 + i * 512 + j];
    }
    __syncthreads();
    float aw = qf[0], ax = -qf[1], ay = -qf[2], az = -qf[3];  // conj
    int h = s >> 3, c = s & 7;
    float acc = 0.f;
#pragma unroll
    for (int tt = 0; tt < 2; tt++) {
        int tile = gr * 2 + tt;
        int j = tile * 64 + s;
        float bw = d_qn[j * 4], bx = d_qn[j * 4 + 1], by = d_qn[j * 4 + 2], bz = d_qn[j * 4 + 3];
        rel_s[gr][s][0] = aw * bw - ax * bx - ay * by - az * bz;
        rel_s[gr][s][1] = aw * bx + ax * bw + ay * bz - az * by;
        rel_s[gr][s][2] = aw * by - ax * bz + ay * bw + az * bx;
        rel_s[gr][s][3] = aw * bz + ax * by - ay * bx + az * bw;
        float dx = d_tr[j * 3] - tf[0], dy = d_tr[j * 3 + 1] - tf[1], dz2 = d_tr[j * 3 + 2] - tf[2];
        float rx, ry, rz;
        qrot(aw, ax, ay, az, dx, dy, dz2, rx, ry, rz);
        rel_s[gr][s][4] = rx; rel_s[gr][s][5] = ry; rel_s[gr][s][6] = rz; rel_s[gr][s][7] = 0.f;
        __syncthreads();
        const float* ah = a_s + h * 512 + tile * 64;
#pragma unroll 16
        for (int jj = 0; jj < 64; jj++) acc += ah[jj] * rel_s[gr][jj][c];
        __syncthreads();
    }
    partial[gr][s] = acc;
    __syncthreads();
    if (t < 64)
        d_orel[i * 64 + t] = partial[0][t] + partial[1][t] + partial[2][t] + partial[3][t];
}

// -------------------- K: epilogue (inv transform, norms, feats, g_out) --------------------
__global__ void __launch_bounds__(256) k_epilogue(const float* __restrict__ W_dz,
                                                  const float* __restrict__ b_dz,
                                                  const float* __restrict__ W_geo,
                                                  float* __restrict__ out_g) {
    __shared__ float ogf[64][17];
    __shared__ float qf[4], tf[3];
    int i = blockIdx.x, t = threadIdx.x;  // 256
    if (t < 4) qf[t] = d_qn[i * 4 + t];
    if (t < 3) tf[t] = d_tr[i * 3 + t];
    __syncthreads();
    float* fr = d_feats + i * 2496;

    // o_pair = za @ W_dz + b_dz
    {
        int h = t >> 5, oc = t & 31;
        const float* za = d_za + i * 1024 + h * 128;
        float acc = b_dz[oc];
#pragma unroll 8
        for (int c = 0; c < 128; c++) acc += za[c] * W_dz[c * 32 + oc];
        fr[h * 312 + oc] = acc;
    }
    // o copy
    for (int idx = t; idx < 1024; idx += 256) {
        int h = idx >> 7, c = idx & 127;
        fr[h * 312 + 32 + c] = d_oall[i * 2048 + h * 256 + c];
    }
    // o_rel copy
    if (t < 64) fr[(t >> 3) * 312 + 160 + (t & 7)] = d_orel[i * 64 + t];
    // o_g inverse transform + norms
    if (t < 64) {
        int h = t >> 3, p = t & 7;
        float qw = qf[0], qx = -qf[1], qy = -qf[2], qz = -qf[3];  // conj
        const float* src = d_oall + i * 2048 + h * 256 + 128 + p * 16;
        float mv[16];
#pragma unroll
        for (int c = 0; c < 16; c++) mv[c] = src[c];
        float o16[16];
        o16[0] = mv[0];
        qrot(qw, qx, qy, qz, mv[1], mv[2], mv[3], o16[1], o16[2], o16[3]);
        qrot(qw, qx, qy, qz, mv[4], mv[5], mv[6], o16[4], o16[5], o16[6]);
        {
            float w10 = mv[10];
            qrot(qw, qx, qy, qz, mv[7] - w10 * tf[0], mv[8] - w10 * tf[1], mv[9] - w10 * tf[2],
                 o16[7], o16[8], o16[9]);
        }
#pragma unroll
        for (int c = 10; c < 16; c++) o16[c] = mv[c];
        float n1 = 0.f, n2 = 0.f;
#pragma unroll
        for (int c = 0; c < 10; c++) n1 += o16[c] * o16[c];
#pragma unroll
        for (int c = 10; c < 16; c++) n2 += o16[c] * o16[c];
        n1 = sqrtf(n1 + 1e-8f);
        n2 = sqrtf(n2 + 1e-8f);
        float* fh = fr + h * 312;
#pragma unroll
        for (int c = 0; c < 16; c++) {
            fh[168 + p * 16 + c] = o16[c];
            ogf[t][c] = o16[c];
        }
        fh[296 + p * 2] = n1;
        fh[296 + p * 2 + 1] = n2;
    }
    __syncthreads();
    // g_out = W_geo @ o_gf
    if (t < 128) {
        int o = t >> 4, c = t & 15;
        float acc = 0.f;
#pragma unroll 16
        for (int k = 0; k < 64; k++) acc += W_geo[o * 64 + k] * ogf[k][c];
        out_g[i * 128 + o * 16 + c] = acc;
    }
}

// -------------------- launch --------------------
extern "C" void kernel_launch(void* const* d_in, const int* in_sizes, int n_in,
                              void* d_out, int out_size) {
    const float* s    = (const float*)d_in[0];
    const float* g    = (const float*)d_in[1];
    const float* z    = (const float*)d_in[2];
    const float* T    = (const float*)d_in[3];
    const float* W_q  = (const float*)d_in[5];
    const float* b_q  = (const float*)d_in[6];
    const float* W_kv = (const float*)d_in[7];
    const float* b_kv = (const float*)d_in[8];
    const float* W_qp = (const float*)d_in[9];
    const float* b_qp = (const float*)d_in[10];
    const float* W_kp = (const float*)d_in[11];
    const float* b_kp = (const float*)d_in[12];
    const float* W_vg = (const float*)d_in[13];
    const float* b_vg = (const float*)d_in[14];
    const float* W_mg = (const float*)d_in[15];
    const float* W_b  = (const float*)d_in[16];
    const float* b_b  = (const float*)d_in[17];
    const float* W_dz = (const float*)d_in[18];
    const float* b_dz = (const float*)d_in[19];
    const float* hwr  = (const float*)d_in[20];
    const float* swr  = (const float*)d_in[21];
    const float* W_out = (const float*)d_in[22];
    const float* b_out = (const float*)d_in[23];
    const float* W_geo = (const float*)d_in[24];
    float* out = (float*)d_out;

    float *p_Wall, *p_ball, *p_proj, *p_qe, *p_ke, *p_logits, *p_vcat, *p_oall, *p_feats, *p_part;
    cudaGetSymbolAddress((void**)&p_Wall, d_Wall);
    cudaGetSymbolAddress((void**)&p_ball, d_ball);
    cudaGetSymbolAddress((void**)&p_proj, d_proj);
    cudaGetSymbolAddress((void**)&p_qe, d_qe);
    cudaGetSymbolAddress((void**)&p_ke, d_ke);
    cudaGetSymbolAddress((void**)&p_logits, d_logits);
    cudaGetSymbolAddress((void**)&p_vcat, d_vcat);
    cudaGetSymbolAddress((void**)&p_oall, d_oall);
    cudaGetSymbolAddress((void**)&p_feats, d_feats);
    cudaGetSymbolAddress((void**)&p_part, d_part);

    // 1. frames + weight packing
    k_frames<<<1, 512>>>(T, hwr);
    k_pack<<<(384 * 3584 + 255) / 256, 256>>>(W_q, b_q, W_kv, b_kv, W_qp, b_qp, W_kp, b_kp, W_vg, b_vg);
    // 2. all projections in ONE GEMM: [512,3584] = s @ Wall + ball
    gemm2<false><<<dim3(56, 8, 1), 256>>>(s, p_Wall, p_proj, p_ball, 384, 0,
                                          384, 3584, 3584, 0, 0, 0);
    // 3. points / extended feats / vcat
    k_points<<<512, 256>>>(g, W_mg);
    // 4. logits = qk*S1 + pt (batched over h, K=160, B transposed)
    gemm2<true><<<dim3(8, 8, 8), 256>>>(p_qe, p_ke, p_logits, nullptr, 160, 0,
                                        160, 160, 512, 81920, 81920, 262144);
    // 5. add z-bias
    k_zbias<<<512, 256>>>(z, W_b, b_b);
    // 6. softmax
    k_softmax<<<dim3(512, 8), 256>>>(swr);
    // 7. apply: o | o_g in one batched GEMM (N=256 per head)
    gemm2<false><<<dim3(4, 8, 8), 256>>>(p_logits, p_vcat, p_oall, nullptr, 512, 0,
                                         512, 2048, 2048, 262144, 256, 256);
    // 8. za, o_rel
    k_za<<<512, 256>>>(z);
    k_orel<<<512, 256>>>();
    // 9. epilogue: transforms, norms, feats, g_out
    k_epilogue<<<512, 256>>>(W_dz, b_dz, W_geo, out + 196608);
    // 10. s_out = feats @ W_out (split-K=4 partials, deterministic reduce)
    gemm2<false><<<dim3(6, 8, 4), 256>>>(p_feats, W_out, p_part, nullptr, 624, 624,
                                         2496, 384, 384, 0, 0, 196608);
    k_red<<<768, 256>>>(b_out, out);
}